// round 8
// baseline (speedup 1.0000x reference)
#include <cuda_runtime.h>
#include <cstdint>

// LoLa: out[m,0]=rowsum(x); out[m,1:513]=x; out[m,513:1025]=x@w
// Grid-specialized. GEMM CTAs: 64x128 tile, 8 warps, warp tile 32x32,
// 3 CTAs/SM (24 warps/SM), KT=16, 4-stage cp.async ring, 1 barrier/ktile.
// Copy CTAs: stream x -> out[1:513] + rowsum.

#define M_TOTAL   131072
#define KDIM      512
#define NOUT      512
#define OUT_COLS  1025

#define MT 64
#define NT 128
#define KT 16
#define NKT (KDIM / KT)       // 32
#define NSTAGE 4

#define XS_STRIDE 20          // words; bank=(20r+c)%32 distinct for frag pattern
#define WS_STRIDE 136         // words; bank=(8k+n)%32 distinct

#define XS_WORDS  (MT * XS_STRIDE)              // 1280
#define WS_WORDS  (KT * WS_STRIDE)              // 2176
#define STAGE_WORDS (XS_WORDS + WS_WORDS)       // 3456
#define SMEM_TOTAL  (NSTAGE * STAGE_WORDS * 4)  // 55296 B -> 3 CTAs = 166 KB

__device__ uint32_t g_w_tf32[KDIM * NOUT];      // w pre-converted to tf32 (RNA)

__device__ __forceinline__ uint32_t f2tf32(float f) {
    uint32_t u;
    asm("cvt.rna.tf32.f32 %0, %1;" : "=r"(u) : "f"(f));
    return u;
}
__device__ __forceinline__ void cp_async16(uint32_t saddr, const void* g) {
    asm volatile("cp.async.cg.shared.global [%0], [%1], 16;" :: "r"(saddr), "l"(g));
}
__device__ __forceinline__ void cp_commit() {
    asm volatile("cp.async.commit_group;" ::);
}
template <int N> __device__ __forceinline__ void cp_wait() {
    asm volatile("cp.async.wait_group %0;" :: "n"(N));
}

__global__ void w_convert_kernel(const float* __restrict__ w) {
    int i = (blockIdx.x * 256 + threadIdx.x) * 4;
    float4 v = *(const float4*)&w[i];
    uint4 t;
    t.x = f2tf32(v.x); t.y = f2tf32(v.y); t.z = f2tf32(v.z); t.w = f2tf32(v.w);
    *(uint4*)&g_w_tf32[i] = t;
}

__global__ __launch_bounds__(256, 3)
void lola_fused_kernel(const float* __restrict__ x,
                       float* __restrict__ out)
{
    extern __shared__ uint32_t smem[];

    const int nb   = blockIdx.x;              // 0..4
    const int mb   = blockIdx.y;              // 0..2047
    const int m0   = mb * MT;
    const int tid  = threadIdx.x;             // 0..255
    const int lane = tid & 31;
    const int warp = tid >> 5;                // 0..7

    // ================= copy + rowsum CTAs =================
    if (nb == 4) {
        #pragma unroll 1
        for (int rr = 0; rr < 8; rr++) {
            const int r = m0 + warp + rr * 8;
            const float4* xr = (const float4*)&x[(size_t)r * KDIM];
            float* orow = &out[(size_t)r * OUT_COLS];
            float s = 0.f;
            #pragma unroll
            for (int j = 0; j < 4; j++) {
                float4 v = xr[lane + 32 * j];
                s += (v.x + v.y) + (v.z + v.w);
                float* o = &orow[1 + (lane + 32 * j) * 4];
                o[0] = v.x; o[1] = v.y; o[2] = v.z; o[3] = v.w;
            }
            s += __shfl_xor_sync(0xffffffffu, s, 16);
            s += __shfl_xor_sync(0xffffffffu, s, 8);
            s += __shfl_xor_sync(0xffffffffu, s, 4);
            s += __shfl_xor_sync(0xffffffffu, s, 2);
            s += __shfl_xor_sync(0xffffffffu, s, 1);
            if (lane == 0) orow[0] = s;
        }
        return;
    }

    // ================= GEMM CTAs =================
    const int n0 = nb * NT;
    const int warp_m = warp & 1;              // m offset *32
    const int warp_n = warp >> 1;             // n offset *32

    float acc[2][4][4];                       // warp tile 32x32
    #pragma unroll
    for (int i = 0; i < 2; i++)
        #pragma unroll
        for (int j = 0; j < 4; j++)
            #pragma unroll
            for (int k = 0; k < 4; k++)
                acc[i][j][k] = 0.0f;

    auto stage = [&](int kt) {
        const int s  = kt & (NSTAGE - 1);
        const int k0 = kt * KT;
        uint32_t xb = (uint32_t)__cvta_generic_to_shared(smem + s * STAGE_WORDS);
        uint32_t wb = xb + XS_WORDS * 4;
        {                                      // A: 64 x 16 fp32 = 256 float4
            int r = tid >> 2, c = (tid & 3) * 4;
            cp_async16(xb + (r * XS_STRIDE + c) * 4,
                       &x[(size_t)(m0 + r) * KDIM + k0 + c]);
        }
        #pragma unroll
        for (int i = 0; i < 2; i++) {          // B: 16 x 128 tf32 = 512 float4
            int idx = tid + i * 256;
            int r = idx >> 5, c = (idx & 31) * 4;
            cp_async16(wb + (r * WS_STRIDE + c) * 4,
                       &g_w_tf32[(size_t)(k0 + r) * NOUT + n0 + c]);
        }
        cp_commit();
    };

    stage(0); stage(1); stage(2);

    #pragma unroll 1
    for (int kt = 0; kt < NKT; kt++) {
        const int s = kt & (NSTAGE - 1);
        const uint32_t* xst = smem + s * STAGE_WORDS;
        const uint32_t* wst = xst + XS_WORDS;

        if (kt < NKT - 3)      cp_wait<2>();
        else if (kt < NKT - 2) cp_wait<1>();
        else                   cp_wait<0>();
        __syncthreads();   // stage kt visible; slot (kt+3)%4 drained (compute kt-1 done)

        if (kt + 3 < NKT) stage(kt + 3);

        #pragma unroll
        for (int kk = 0; kk < KT; kk += 8) {
            uint32_t bfrag[4][2];
            #pragma unroll
            for (int nf = 0; nf < 4; nf++) {
                int col = warp_n * 32 + nf * 8 + (lane >> 2);
                bfrag[nf][0] = wst[(kk + (lane & 3)) * WS_STRIDE + col];
                bfrag[nf][1] = wst[(kk + (lane & 3) + 4) * WS_STRIDE + col];
            }
            uint32_t afrag[2][4];
            #pragma unroll
            for (int mf = 0; mf < 2; mf++) {
                int row = warp_m * 32 + mf * 16 + (lane >> 2);
                int c0  = kk + (lane & 3);
                afrag[mf][0] = xst[row * XS_STRIDE + c0];
                afrag[mf][1] = xst[(row + 8) * XS_STRIDE + c0];
                afrag[mf][2] = xst[row * XS_STRIDE + c0 + 4];
                afrag[mf][3] = xst[(row + 8) * XS_STRIDE + c0 + 4];
            }
            #pragma unroll
            for (int mf = 0; mf < 2; mf++) {
                #pragma unroll
                for (int nf = 0; nf < 4; nf++) {
                    asm volatile(
                        "mma.sync.aligned.m16n8k8.row.col.f32.tf32.tf32.f32 "
                        "{%0,%1,%2,%3}, {%4,%5,%6,%7}, {%8,%9}, {%0,%1,%2,%3};"
                        : "+f"(acc[mf][nf][0]), "+f"(acc[mf][nf][1]),
                          "+f"(acc[mf][nf][2]), "+f"(acc[mf][nf][3])
                        : "r"(afrag[mf][0]), "r"(afrag[mf][1]),
                          "r"(afrag[mf][2]), "r"(afrag[mf][3]),
                          "r"(bfrag[nf][0]), "r"(bfrag[nf][1]));
                }
            }
        }
    }

    // ---- epilogue: GEMM columns ----
    #pragma unroll
    for (int mf = 0; mf < 2; mf++) {
        int row = m0 + warp_m * 32 + mf * 16 + (lane >> 2);
        #pragma unroll
        for (int nf = 0; nf < 4; nf++) {
            int col = 513 + n0 + warp_n * 32 + nf * 8 + (lane & 3) * 2;
            out[(size_t)row * OUT_COLS + col]           = acc[mf][nf][0];
            out[(size_t)row * OUT_COLS + col + 1]       = acc[mf][nf][1];
            out[(size_t)(row + 8) * OUT_COLS + col]     = acc[mf][nf][2];
            out[(size_t)(row + 8) * OUT_COLS + col + 1] = acc[mf][nf][3];
        }
    }
}

extern "C" void kernel_launch(void* const* d_in, const int* in_sizes, int n_in,
                              void* d_out, int out_size)
{
    const float* x = (const float*)d_in[0];   // (131072, 512)
    const float* w = (const float*)d_in[1];   // (512, 512)
    float* out = (float*)d_out;               // (131072, 1025)

    w_convert_kernel<<<256, 256>>>(w);
    cudaFuncSetAttribute(lola_fused_kernel,
                         cudaFuncAttributeMaxDynamicSharedMemorySize, SMEM_TOTAL);
    dim3 grid(5, M_TOTAL / MT);               // (4 GEMM + 1 copy, 2048)
    lola_fused_kernel<<<grid, 256, SMEM_TOTAL>>>(x, out);
}

// round 9
// speedup vs baseline: 1.4602x; 1.4602x over previous
#include <cuda_runtime.h>
#include <cuda_fp16.h>
#include <cstdint>

// LoLa: out[m,0]=rowsum(x); out[m,1:513]=x; out[m,513:1025]=x@w
// fp16 m16n8k16 HMMA (fp32 acc). x,w pre-converted to packed half2 (pairs on k).
// GEMM CTAs: 128x128 tile, 8 warps, warp tile 64x32, 3-stage cp.async ring,
// 1 barrier/ktile, 2 CTAs/SM. Copy CTAs (nb==4) stream x->out[1:513] + rowsum.

#define M_TOTAL   131072
#define KDIM      512
#define NOUT      512
#define OUT_COLS  1025

#define MT 128
#define NT 128
#define KT 32                  // k elements per tile = 16 half2 words
#define KW (KT / 2)            // 16 word-cols per ktile
#define NKT (KDIM / KT)        // 16
#define NSTAGE 3

#define XS_STRIDE 20           // words; banks (20r+c)%32 all-distinct for frag quads
#define WS_STRIDE 136          // words; banks (8k+n)%32 all-distinct

#define XS_WORDS  (MT * XS_STRIDE)              // 2560
#define WS_WORDS  (KW * WS_STRIDE)              // 2176
#define STAGE_WORDS (XS_WORDS + WS_WORDS)       // 4736
#define SMEM_TOTAL  (NSTAGE * STAGE_WORDS * 4)  // 56832 B -> 2 CTAs/SM

// packed half2 operands (low half = even k)
__device__ uint32_t g_x_f16[M_TOTAL * KDIM / 2];   // [m][k/2], 128 MB
__device__ uint32_t g_w_f16[KDIM / 2 * NOUT];      // [k/2][n], 0.5 MB

__device__ __forceinline__ uint32_t packh2(float lo, float hi) {
    __half2 h = __floats2half2_rn(lo, hi);
    return *(uint32_t*)&h;
}
__device__ __forceinline__ void cp_async16(uint32_t saddr, const void* g) {
    asm volatile("cp.async.cg.shared.global [%0], [%1], 16;" :: "r"(saddr), "l"(g));
}
__device__ __forceinline__ void cp_commit() {
    asm volatile("cp.async.commit_group;" ::);
}
template <int N> __device__ __forceinline__ void cp_wait() {
    asm volatile("cp.async.wait_group %0;" :: "n"(N));
}

// x -> packed half2 pairs: 8 elements (2 float4) -> uint4 per thread
__global__ void x_convert_kernel(const float* __restrict__ x) {
    size_t i = ((size_t)blockIdx.x * 256 + threadIdx.x) * 8;
    float4 a = *(const float4*)&x[i];
    float4 b = *(const float4*)&x[i + 4];
    uint4 o;
    o.x = packh2(a.x, a.y); o.y = packh2(a.z, a.w);
    o.z = packh2(b.x, b.y); o.w = packh2(b.z, b.w);
    *(uint4*)&g_x_f16[i / 2] = o;
}

// w -> packed half2 pairs along k: g_w_f16[kp*512+n] = (w[2kp][n], w[2kp+1][n])
__global__ void w_convert_kernel(const float* __restrict__ w) {
    int idx = blockIdx.x * 256 + threadIdx.x;     // 0..131071
    int kp = idx >> 9, n = idx & 511;
    g_w_f16[idx] = packh2(w[(size_t)(2 * kp) * NOUT + n],
                          w[(size_t)(2 * kp + 1) * NOUT + n]);
}

__global__ __launch_bounds__(256, 2)
void lola_fused_kernel(const float* __restrict__ x,
                       float* __restrict__ out)
{
    extern __shared__ uint32_t smem[];

    const int nb   = blockIdx.x;              // 0..4
    const int mb   = blockIdx.y;              // 0..1023
    const int m0   = mb * MT;
    const int tid  = threadIdx.x;             // 0..255
    const int lane = tid & 31;
    const int warp = tid >> 5;                // 0..7

    // ================= copy + rowsum CTAs =================
    if (nb == 4) {
        #pragma unroll 1
        for (int rr = 0; rr < 16; rr++) {
            const int r = m0 + warp + rr * 8;
            const float4* xr = (const float4*)&x[(size_t)r * KDIM];
            float* orow = &out[(size_t)r * OUT_COLS];
            float s = 0.f;
            #pragma unroll
            for (int j = 0; j < 4; j++) {
                float4 v = xr[lane + 32 * j];
                s += (v.x + v.y) + (v.z + v.w);
                float* o = &orow[1 + (lane + 32 * j) * 4];
                o[0] = v.x; o[1] = v.y; o[2] = v.z; o[3] = v.w;
            }
            s += __shfl_xor_sync(0xffffffffu, s, 16);
            s += __shfl_xor_sync(0xffffffffu, s, 8);
            s += __shfl_xor_sync(0xffffffffu, s, 4);
            s += __shfl_xor_sync(0xffffffffu, s, 2);
            s += __shfl_xor_sync(0xffffffffu, s, 1);
            if (lane == 0) orow[0] = s;
        }
        return;
    }

    // ================= GEMM CTAs =================
    const int n0 = nb * NT;
    const int warp_m = warp & 1;              // m offset *64
    const int warp_n = warp >> 1;             // n offset *32

    float acc[4][4][4];                       // warp tile 64x32
    #pragma unroll
    for (int i = 0; i < 4; i++)
        #pragma unroll
        for (int j = 0; j < 4; j++)
            #pragma unroll
            for (int k = 0; k < 4; k++)
                acc[i][j][k] = 0.0f;

    auto stage = [&](int kt) {
        const int s   = kt % NSTAGE;
        const int kw0 = kt * KW;               // word offset in k
        uint32_t xb = (uint32_t)__cvta_generic_to_shared(smem + s * STAGE_WORDS);
        uint32_t wb = xb + XS_WORDS * 4;
        #pragma unroll
        for (int i = 0; i < 2; i++) {          // A: 128 x 16 words = 512 chunks
            int idx = tid + i * 256;           // 0..511
            int r = idx >> 2, c = (idx & 3) * 4;
            cp_async16(xb + (r * XS_STRIDE + c) * 4,
                       &g_x_f16[(size_t)(m0 + r) * (KDIM / 2) + kw0 + c]);
        }
        #pragma unroll
        for (int i = 0; i < 2; i++) {          // B: 16 x 128 words = 512 chunks
            int idx = tid + i * 256;
            int r = idx >> 5, c = (idx & 31) * 4;
            cp_async16(wb + (r * WS_STRIDE + c) * 4,
                       &g_w_f16[(size_t)(kw0 + r) * NOUT + n0 + c]);
        }
        cp_commit();
    };

    stage(0); stage(1);

    #pragma unroll 1
    for (int kt = 0; kt < NKT; kt++) {
        const int s = kt % NSTAGE;
        const uint32_t* xst = smem + s * STAGE_WORDS;
        const uint32_t* wst = xst + XS_WORDS;

        if (kt + 2 < NKT) cp_wait<1>(); else cp_wait<0>();
        __syncthreads();   // stage kt visible; slot (kt+2)%3 free (compute kt-1 done)

        if (kt + 2 < NKT) stage(kt + 2);

        #pragma unroll
        for (int kk = 0; kk < KW; kk += 8) {   // 2 k16-steps per ktile
            uint32_t bfrag[4][2];
            #pragma unroll
            for (int nf = 0; nf < 4; nf++) {
                int col = warp_n * 32 + nf * 8 + (lane >> 2);
                bfrag[nf][0] = wst[(kk + (lane & 3)) * WS_STRIDE + col];
                bfrag[nf][1] = wst[(kk + (lane & 3) + 4) * WS_STRIDE + col];
            }
            uint32_t afrag[4][4];
            #pragma unroll
            for (int mf = 0; mf < 4; mf++) {
                int row = warp_m * 64 + mf * 16 + (lane >> 2);
                int c0  = kk + (lane & 3);
                afrag[mf][0] = xst[row * XS_STRIDE + c0];
                afrag[mf][1] = xst[(row + 8) * XS_STRIDE + c0];
                afrag[mf][2] = xst[row * XS_STRIDE + c0 + 4];
                afrag[mf][3] = xst[(row + 8) * XS_STRIDE + c0 + 4];
            }
            #pragma unroll
            for (int mf = 0; mf < 4; mf++) {
                #pragma unroll
                for (int nf = 0; nf < 4; nf++) {
                    asm volatile(
                        "mma.sync.aligned.m16n8k16.row.col.f32.f16.f16.f32 "
                        "{%0,%1,%2,%3}, {%4,%5,%6,%7}, {%8,%9}, {%0,%1,%2,%3};"
                        : "+f"(acc[mf][nf][0]), "+f"(acc[mf][nf][1]),
                          "+f"(acc[mf][nf][2]), "+f"(acc[mf][nf][3])
                        : "r"(afrag[mf][0]), "r"(afrag[mf][1]),
                          "r"(afrag[mf][2]), "r"(afrag[mf][3]),
                          "r"(bfrag[nf][0]), "r"(bfrag[nf][1]));
                }
            }
        }
    }

    // ---- epilogue: GEMM columns ----
    #pragma unroll
    for (int mf = 0; mf < 4; mf++) {
        int row = m0 + warp_m * 64 + mf * 16 + (lane >> 2);
        #pragma unroll
        for (int nf = 0; nf < 4; nf++) {
            int col = 513 + n0 + warp_n * 32 + nf * 8 + (lane & 3) * 2;
            out[(size_t)row * OUT_COLS + col]           = acc[mf][nf][0];
            out[(size_t)row * OUT_COLS + col + 1]       = acc[mf][nf][1];
            out[(size_t)(row + 8) * OUT_COLS + col]     = acc[mf][nf][2];
            out[(size_t)(row + 8) * OUT_COLS + col + 1] = acc[mf][nf][3];
        }
    }
}

extern "C" void kernel_launch(void* const* d_in, const int* in_sizes, int n_in,
                              void* d_out, int out_size)
{
    const float* x = (const float*)d_in[0];   // (131072, 512)
    const float* w = (const float*)d_in[1];   // (512, 512)
    float* out = (float*)d_out;               // (131072, 1025)

    w_convert_kernel<<<512, 256>>>(w);        // 131072 half2 words
    x_convert_kernel<<<32768, 256>>>(x);      // 64M elements, 8 per thread
    cudaFuncSetAttribute(lola_fused_kernel,
                         cudaFuncAttributeMaxDynamicSharedMemorySize, SMEM_TOTAL);
    dim3 grid(5, M_TOTAL / MT);               // (4 GEMM + 1 copy, 1024)
    lola_fused_kernel<<<grid, 256, SMEM_TOTAL>>>(x, out);
}